// round 5
// baseline (speedup 1.0000x reference)
#include <cuda_runtime.h>
#include <cuda_fp16.h>
#include <cstdint>

#define NB 1024
#define NT 256
#define NE 300
#define LOG2E 1.4426950408889634
#define INVL2E 0.6931471805599453f
#define ESTRIDE 264   // half elements per E row; 132 words -> 4j mod 32 bank map, conflict-free LDS.128

// smem layout (dynamic): E[256*264] half | rs[256] | p2[256] | Rr[256] | us[256] | red[8*6]
#define SM_E_BYTES (NT * ESTRIDE * 2)
#define SM_TOTAL   (SM_E_BYTES + 4 * NT * 4 + 8 * 6 * 4)

// ---------------- static device precompute (no allocations allowed) ----------------
__device__ float g_M[NT * NT];       // M[t][f] = sum_e TE[e][t] * Wf[f][e]
__device__ float g_G2[NT * NT];      // (M M^T) * log2(e)
__device__ float g_v2[NT];           // (M b_f) * log2(e)
__device__ float g_c2;               // (b_f . b_f) * log2(e)

__device__ __forceinline__ float fast_exp2(float x) {
    float y; asm("ex2.approx.f32 %0, %1;" : "=f"(y) : "f"(x)); return y;
}
__device__ __forceinline__ float fast_rcp(float x) {
    float y; asm("rcp.approx.f32 %0, %1;" : "=f"(y) : "f"(x)); return y;
}

// ---------------- precompute M (fp64 accumulate for accuracy) ----------------
__global__ void k_M(const float* __restrict__ te, const float* __restrict__ wf) {
    __shared__ float tesh[NE];
    int t = blockIdx.x, f = threadIdx.x;
    for (int e = f; e < NE; e += NT) tesh[e] = te[e * NT + t];
    __syncthreads();
    const float* wrow = wf + f * NE;
    double acc = 0.0;
    for (int e = 0; e < NE; e++) acc += (double)tesh[e] * (double)wrow[e];
    g_M[t * NT + f] = (float)acc;
}

// ---------------- precompute G2 = (M M^T)*log2e, v2, c2 ----------------
__global__ void k_G(const float* __restrict__ bf) {
    __shared__ float mi[NT];
    __shared__ float bsh[NT];
    int i = blockIdx.x, j = threadIdx.x;
    mi[j] = g_M[i * NT + j];
    if (i == 0) bsh[j] = bf[j];
    __syncthreads();
    const float* mj = g_M + j * NT;
    double acc = 0.0;
    for (int k = 0; k < NT; k++) acc += (double)mi[k] * (double)mj[k];
    g_G2[i * NT + j] = (float)(acc * LOG2E);
    if (i == 0) {
        double av = 0.0;
        for (int k = 0; k < NT; k++) av += (double)mj[k] * (double)bsh[k];
        g_v2[j] = (float)(av * LOG2E);
        if (j == 0) {
            double cc = 0.0;
            for (int k = 0; k < NT; k++) cc += (double)bsh[k] * (double)bsh[k];
            g_c2 = (float)(cc * LOG2E);
        }
    }
}

// ---------------- fused per-batch kernel ----------------
// log2-domain logits: A2[r][c] = (w_c*rs[r])*G2[r][c] + (p2[r] + base_c)
// softmax over r (axis=1). Everything downstream of the softmax is expressed
// in quadratic forms with G (no M, no global scratch):
//   y = G rtheta (accumulated inside pass 2), z = G u (pass 4),
//   num   = rGu + S*(r.v) + T*(u.v) + T*S*c
//   n1^2  = rGr + 2T*(r.v) + T^2 c
//   n2^2  = uGu + 2S*(u.v) + S^2 c
__global__ void __launch_bounds__(NT) k_fused(const float* __restrict__ req,
                                              const float* __restrict__ wsdl,
                                              float* __restrict__ out) {
    extern __shared__ __align__(16) unsigned char smraw[];
    __half* E  = (__half*)smraw;
    float* rs  = (float*)(smraw + SM_E_BYTES);
    float* p2  = rs + NT;
    float* Rr  = p2 + NT;
    float* us  = Rr + NT;
    float* red = us + NT;   // 8 warps * 6 values

    int b = blockIdx.x, c = threadIdx.x;

    float w_c = wsdl[b * NT + c];
    float r_c = req[b * NT + c];
    float v2c = g_v2[c];
    rs[c] = r_c;
    p2[c] = r_c * v2c;
    __syncthreads();
    float base = fmaf(w_c, v2c, g_c2);
    const float* Gc = g_G2 + c;

    // ---- pass 1: exact column max (coalesced G reads: warp = one G row) ----
    float mx = -1e30f;
#pragma unroll 16
    for (int r = 0; r < NT; r++) {
        float a = fmaf(w_c * rs[r], Gc[(size_t)r * NT], p2[r] + base);
        mx = fmaxf(mx, a);
    }

    // ---- pass 2: exp2 weights -> shared E (fp16), column sum Z, y = G*rtheta ----
    float Z = 0.0f, y2 = 0.0f;
#pragma unroll 16
    for (int r = 0; r < NT; r++) {
        float g = Gc[(size_t)r * NT];
        float rr = rs[r];
        float a = fmaf(w_c * rr, g, p2[r] + base);
        float e = fast_exp2(a - mx);
        Z += e;
        y2 = fmaf(g, rr, y2);                  // (G2 rtheta)_c, carries LOG2E
        E[r * ESTRIDE + c] = __float2half(e);
    }
    Rr[c] = fast_rcp(Z);
    __syncthreads();

    // ---- pass 3: row sums from shared E (thread c owns row c), conflict-free ----
    const uint4* er = (const uint4*)(E + (size_t)c * ESTRIDE);
    const float4* R4 = (const float4*)Rr;
    float s = 0.0f;
#pragma unroll 8
    for (int q = 0; q < NT / 8; q++) {
        uint4 u4 = er[q];
        float2 e0 = __half22float2(*(__half2*)&u4.x);
        float2 e1 = __half22float2(*(__half2*)&u4.y);
        float2 e2 = __half22float2(*(__half2*)&u4.z);
        float2 e3 = __half22float2(*(__half2*)&u4.w);
        float4 ra = R4[2 * q], rb = R4[2 * q + 1];
        s = fmaf(e0.x, ra.x, s); s = fmaf(e0.y, ra.y, s);
        s = fmaf(e1.x, ra.z, s); s = fmaf(e1.y, ra.w, s);
        s = fmaf(e2.x, rb.x, s); s = fmaf(e2.y, rb.y, s);
        s = fmaf(e3.x, rb.z, s); s = fmaf(e3.y, rb.w, s);
    }
    float u = s * r_c;
    us[c] = u;
    __syncthreads();

    // ---- pass 4: z = G * u ----
    float z2 = 0.0f;
#pragma unroll 16
    for (int r = 0; r < NT; r++) {
        z2 = fmaf(Gc[(size_t)r * NT], us[r], z2);
    }

    // ---- reductions: T0=r.y T1=u.y T2=u.z T3=r.v2 T4=u.v2 T5=S ----
    float t0 = r_c * y2;
    float t1 = u * y2;
    float t2 = u * z2;
    float t3 = r_c * v2c;
    float t4 = u * v2c;
    float t5 = s;
#pragma unroll
    for (int o = 16; o; o >>= 1) {
        t0 += __shfl_down_sync(0xffffffffu, t0, o);
        t1 += __shfl_down_sync(0xffffffffu, t1, o);
        t2 += __shfl_down_sync(0xffffffffu, t2, o);
        t3 += __shfl_down_sync(0xffffffffu, t3, o);
        t4 += __shfl_down_sync(0xffffffffu, t4, o);
        t5 += __shfl_down_sync(0xffffffffu, t5, o);
    }
    if ((c & 31) == 0) {
        int w = c >> 5;
        red[w * 6 + 0] = t0; red[w * 6 + 1] = t1; red[w * 6 + 2] = t2;
        red[w * 6 + 3] = t3; red[w * 6 + 4] = t4; red[w * 6 + 5] = t5;
    }
    __syncthreads();
    if (c == 0) {
        float T0 = 0, T1 = 0, T2 = 0, T3 = 0, T4 = 0, S = 0;
#pragma unroll
        for (int w = 0; w < 8; w++) {
            T0 += red[w * 6 + 0]; T1 += red[w * 6 + 1]; T2 += red[w * 6 + 2];
            T3 += red[w * 6 + 3]; T4 += red[w * 6 + 4]; S  += red[w * 6 + 5];
        }
        float c_un = g_c2 * INVL2E;
        const float Tf = (float)NT;
        float num = (T1 + S * T3 + Tf * T4) * INVL2E + Tf * S * c_un;
        float n1s = (T0 + 2.0f * Tf * T3) * INVL2E + Tf * Tf * c_un;
        float n2s = (T2 + 2.0f * S * T4) * INVL2E + S * S * c_un;
        float denom = fmaxf(sqrtf(n1s) * sqrtf(n2s), 1e-8f * Tf * Tf);
        out[b] = 3.0f * num / denom;
    }
}

extern "C" void kernel_launch(void* const* d_in, const int* in_sizes, int n_in,
                              void* d_out, int out_size) {
    const float* req  = (const float*)d_in[0];   // [B,T]
    const float* wsdl = (const float*)d_in[1];   // [B,T]
    const float* te   = (const float*)d_in[2];   // [E,T]
    const float* wf   = (const float*)d_in[3];   // [T,E]
    const float* bf   = (const float*)d_in[4];   // [T]
    float* out = (float*)d_out;                  // [B]

    cudaFuncSetAttribute(k_fused, cudaFuncAttributeMaxDynamicSharedMemorySize, SM_TOTAL);

    k_M<<<NT, NT>>>(te, wf);
    k_G<<<NT, NT>>>(bf);
    k_fused<<<NB, NT, SM_TOTAL>>>(req, wsdl, out);
}

// round 6
// speedup vs baseline: 2.3427x; 2.3427x over previous
#include <cuda_runtime.h>
#include <cuda_fp16.h>
#include <cstdint>

#define NB 1024
#define NT 256
#define NE 300
#define LOG2E 1.4426950408889634
#define INVL2E 0.6931471805599453f
#define ESTRIDE 264   // half elems per E row: 132 words -> 4j mod 32 bank map, conflict-free LDS.128
#define NTH 512
#define RH 128        // rows per half-thread
#define CH 32         // online-softmax chunk (rows)

// ---- dynamic smem layout ----
#define SM_E_BYTES   (NT * ESTRIDE * 2)            // 135168
#define SM_RS        (SM_E_BYTES)                  // float[256]
#define SM_P2        (SM_RS + NT * 4)
#define SM_MK        (SM_P2 + NT * 4)              // float[8][256] mk -> Rk in place
#define SM_MH        (SM_MK + 8 * NT * 4)          // float[2][256]
#define SM_ZH        (SM_MH + 2 * NT * 4)
#define SM_YH        (SM_ZH + 2 * NT * 4)
#define SM_SH        (SM_YH + 2 * NT * 4)          // float[2][256], reused for z partials
#define SM_US        (SM_SH + 2 * NT * 4)          // float[256]
#define SM_RED       (SM_US + NT * 4)              // float[16*6]
#define SM_TOTAL     (SM_RED + 16 * 6 * 4)

// ---------------- static device precompute (no allocations allowed) ----------------
__device__ float g_M[NT * NT];       // M[t][f] = sum_e TE[e][t] * Wf[f][e]
__device__ float g_G2[NT * NT];      // (M M^T) * log2(e)   (symmetric)
__device__ float g_v2[NT];           // (M b_f) * log2(e)
__device__ float g_c2;               // (b_f . b_f) * log2(e)

__device__ __forceinline__ float fast_exp2(float x) {
    float y; asm("ex2.approx.f32 %0, %1;" : "=f"(y) : "f"(x)); return y;
}
__device__ __forceinline__ float fast_rcp(float x) {
    float y; asm("rcp.approx.f32 %0, %1;" : "=f"(y) : "f"(x)); return y;
}

// ---------------- precompute M (fp32, 4-way interleaved accumulation) ----------------
__global__ void k_M(const float* __restrict__ te, const float* __restrict__ wf) {
    __shared__ float tesh[NE];
    int t = blockIdx.x, f = threadIdx.x;
    for (int e = f; e < NE; e += NT) tesh[e] = te[e * NT + t];
    __syncthreads();
    const float* wrow = wf + f * NE;
    float a0 = 0.f, a1 = 0.f, a2 = 0.f, a3 = 0.f;
#pragma unroll 5
    for (int e = 0; e < NE; e += 4) {           // NE = 300, divisible by 4
        a0 = fmaf(tesh[e + 0], wrow[e + 0], a0);
        a1 = fmaf(tesh[e + 1], wrow[e + 1], a1);
        a2 = fmaf(tesh[e + 2], wrow[e + 2], a2);
        a3 = fmaf(tesh[e + 3], wrow[e + 3], a3);
    }
    g_M[t * NT + f] = (a0 + a1) + (a2 + a3);
}

// ---------------- precompute G2 = (M M^T)*log2e, v2, c2 (fp32) ----------------
__global__ void k_G(const float* __restrict__ bf) {
    __shared__ float mi[NT];
    __shared__ float bsh[NT];
    int i = blockIdx.x, j = threadIdx.x;
    mi[j] = g_M[i * NT + j];
    if (i == 0) bsh[j] = bf[j];
    __syncthreads();
    const float* mj = g_M + j * NT;
    float a0 = 0.f, a1 = 0.f, a2 = 0.f, a3 = 0.f;
#pragma unroll 8
    for (int k = 0; k < NT; k += 4) {
        a0 = fmaf(mi[k + 0], mj[k + 0], a0);
        a1 = fmaf(mi[k + 1], mj[k + 1], a1);
        a2 = fmaf(mi[k + 2], mj[k + 2], a2);
        a3 = fmaf(mi[k + 3], mj[k + 3], a3);
    }
    g_G2[i * NT + j] = ((a0 + a1) + (a2 + a3)) * (float)LOG2E;
    if (i == 0) {
        float v0 = 0.f, v1 = 0.f;
#pragma unroll 8
        for (int k = 0; k < NT; k += 2) {
            v0 = fmaf(mj[k], bsh[k], v0);
            v1 = fmaf(mj[k + 1], bsh[k + 1], v1);
        }
        g_v2[j] = (v0 + v1) * (float)LOG2E;
        if (j == 0) {
            float c0 = 0.f;
            for (int k = 0; k < NT; k++) c0 = fmaf(bsh[k], bsh[k], c0);
            g_c2 = c0 * (float)LOG2E;
        }
    }
}

// ---------------- fused per-batch kernel (512 threads: column c, row-half h) -------
// log2-domain logits A2[r][c] = (w_c*rs[r])*G2[r][c] + p2[r] + base_c
// Online chunked softmax over r (chunk=32): store e=2^(a-m_k) fp16, chunk running
// max m_k; correction 2^(m_k-mx)*invZ folded into 8 normalizer vectors Rk[k][c].
// Then quadratic forms with G (y=G*rtheta piggybacked, z=G*u one extra pass).
__global__ void __launch_bounds__(NTH) k_fused(const float* __restrict__ req,
                                               const float* __restrict__ wsdl,
                                               float* __restrict__ out) {
    extern __shared__ __align__(16) unsigned char smraw[];
    __half* E   = (__half*)smraw;
    float* rs   = (float*)(smraw + SM_RS);
    float* p2   = (float*)(smraw + SM_P2);
    float* mkRk = (float*)(smraw + SM_MK);
    float* mh   = (float*)(smraw + SM_MH);
    float* Zh   = (float*)(smraw + SM_ZH);
    float* yh   = (float*)(smraw + SM_YH);
    float* sh   = (float*)(smraw + SM_SH);
    float* us   = (float*)(smraw + SM_US);
    float* red  = (float*)(smraw + SM_RED);

    int tid = threadIdx.x;
    int c = tid & (NT - 1);
    int h = tid >> 8;
    int b = blockIdx.x;

    float w_c = wsdl[b * NT + c];
    float r_c = req[b * NT + c];
    float v2c = g_v2[c];
    if (h == 0) { rs[c] = r_c; p2[c] = r_c * v2c; }
    __syncthreads();
    float base = fmaf(w_c, v2c, g_c2);
    const float* Gc = g_G2 + c;

    // ---- pass A: online max + exp + y2 partials over rows [h*128, h*128+128) ----
    float m = -1e30f, Z = 0.f, y2 = 0.f;
    int r0 = h * RH;
#pragma unroll
    for (int k = 0; k < RH / CH; k++) {
        int rb = r0 + k * CH;
        float a[CH];
        float cm = -1e30f;
#pragma unroll
        for (int i = 0; i < CH; i++) {
            float g  = Gc[(size_t)(rb + i) * NT];
            float rr = rs[rb + i];
            a[i] = fmaf(w_c * rr, g, p2[rb + i] + base);
            y2 = fmaf(g, rr, y2);
            cm = fmaxf(cm, a[i]);
        }
        float mn = fmaxf(m, cm);
        Z *= fast_exp2(m - mn);   // first chunk: 0 * exp2(-huge) = 0, fine
        m = mn;
        __half* Eb = E + (size_t)rb * ESTRIDE + c;
#pragma unroll
        for (int i = 0; i < CH; i++) {
            float e = fast_exp2(a[i] - m);
            Z += e;
            Eb[i * ESTRIDE] = __float2half(e);
        }
        mkRk[(h * 4 + k) * NT + c] = m;
    }
    mh[h * NT + c] = m; Zh[h * NT + c] = Z; yh[h * NT + c] = y2;
    __syncthreads();

    // ---- combine column stats (redundant per h) + build Rk in place ----
    float m0 = mh[c], m1 = mh[NT + c];
    float mx = fmaxf(m0, m1);
    float Zc = Zh[c] * fast_exp2(m0 - mx) + Zh[NT + c] * fast_exp2(m1 - mx);
    float invZ = fast_rcp(Zc);
    float y2t = yh[c] + yh[NT + c];
#pragma unroll
    for (int k = 0; k < 4; k++) {
        int kk = h * 4 + k;
        mkRk[kk * NT + c] = fast_exp2(mkRk[kk * NT + c] - mx) * invZ;
    }
    __syncthreads();

    // ---- pass B: row sums from shared E; thread (j=c, h) sums cols [128h,128h+128) --
    {
        int j = c;
        const uint4*  er = (const uint4*)(E + (size_t)j * ESTRIDE + h * RH);
        const float4* rk = (const float4*)(mkRk + (j >> 5) * NT + h * RH);
        float s = 0.f;
#pragma unroll
        for (int q = 0; q < RH / 8; q++) {
            uint4 u4 = er[q];
            float4 ra = rk[2 * q], rb2 = rk[2 * q + 1];
            float2 e0 = __half22float2(*(__half2*)&u4.x);
            float2 e1 = __half22float2(*(__half2*)&u4.y);
            float2 e2 = __half22float2(*(__half2*)&u4.z);
            float2 e3 = __half22float2(*(__half2*)&u4.w);
            s = fmaf(e0.x, ra.x, s);  s = fmaf(e0.y, ra.y, s);
            s = fmaf(e1.x, ra.z, s);  s = fmaf(e1.y, ra.w, s);
            s = fmaf(e2.x, rb2.x, s); s = fmaf(e2.y, rb2.y, s);
            s = fmaf(e3.x, rb2.z, s); s = fmaf(e3.y, rb2.w, s);
        }
        sh[h * NT + j] = s;
    }
    __syncthreads();
    float st = sh[c] + sh[NT + c];     // s for row c
    float u  = st * r_c;               // u_j = s_j * rtheta_j  (row index == c)
    if (h == 0) us[c] = u;
    __syncthreads();

    // ---- pass C: z = G*u partials over rows half ----
    float z2 = 0.f;
#pragma unroll 16
    for (int r = r0; r < r0 + RH; r++) {
        z2 = fmaf(Gc[(size_t)r * NT], us[r], z2);
    }
    sh[h * NT + c] = z2;               // reuse sh (all threads past st-read barrier)
    __syncthreads();
    float z2t = sh[c] + sh[NT + c];

    // ---- reductions: T0=r.y T1=u.y T2=u.z T3=r.v2 T4=u.v2 T5=S (h==0 contributes) --
    float t0 = 0.f, t1 = 0.f, t2 = 0.f, t3 = 0.f, t4 = 0.f, t5 = 0.f;
    if (h == 0) {
        t0 = r_c * y2t; t1 = u * y2t; t2 = u * z2t;
        t3 = r_c * v2c; t4 = u * v2c; t5 = st;
    }
#pragma unroll
    for (int o = 16; o; o >>= 1) {
        t0 += __shfl_down_sync(0xffffffffu, t0, o);
        t1 += __shfl_down_sync(0xffffffffu, t1, o);
        t2 += __shfl_down_sync(0xffffffffu, t2, o);
        t3 += __shfl_down_sync(0xffffffffu, t3, o);
        t4 += __shfl_down_sync(0xffffffffu, t4, o);
        t5 += __shfl_down_sync(0xffffffffu, t5, o);
    }
    if ((tid & 31) == 0) {
        int w = tid >> 5;
        red[w * 6 + 0] = t0; red[w * 6 + 1] = t1; red[w * 6 + 2] = t2;
        red[w * 6 + 3] = t3; red[w * 6 + 4] = t4; red[w * 6 + 5] = t5;
    }
    __syncthreads();
    if (tid == 0) {
        float T0 = 0, T1 = 0, T2 = 0, T3 = 0, T4 = 0, S = 0;
#pragma unroll
        for (int w = 0; w < 16; w++) {
            T0 += red[w * 6 + 0]; T1 += red[w * 6 + 1]; T2 += red[w * 6 + 2];
            T3 += red[w * 6 + 3]; T4 += red[w * 6 + 4]; S  += red[w * 6 + 5];
        }
        float c_un = g_c2 * INVL2E;
        const float Tf = (float)NT;
        float num = (T1 + S * T3 + Tf * T4) * INVL2E + Tf * S * c_un;
        float n1s = (T0 + 2.0f * Tf * T3) * INVL2E + Tf * Tf * c_un;
        float n2s = (T2 + 2.0f * S * T4) * INVL2E + S * S * c_un;
        float denom = fmaxf(sqrtf(n1s) * sqrtf(n2s), 1e-8f * Tf * Tf);
        out[b] = 3.0f * num / denom;
    }
}

extern "C" void kernel_launch(void* const* d_in, const int* in_sizes, int n_in,
                              void* d_out, int out_size) {
    const float* req  = (const float*)d_in[0];   // [B,T]
    const float* wsdl = (const float*)d_in[1];   // [B,T]
    const float* te   = (const float*)d_in[2];   // [E,T]
    const float* wf   = (const float*)d_in[3];   // [T,E]
    const float* bf   = (const float*)d_in[4];   // [T]
    float* out = (float*)d_out;                  // [B]

    cudaFuncSetAttribute(k_fused, cudaFuncAttributeMaxDynamicSharedMemorySize, SM_TOTAL);

    k_M<<<NT, NT>>>(te, wf);
    k_G<<<NT, NT>>>(bf);
    k_fused<<<NB, NTH, SM_TOTAL>>>(req, wsdl, out);
}

// round 7
// speedup vs baseline: 3.9176x; 1.6722x over previous
#include <cuda_runtime.h>
#include <cuda_fp16.h>
#include <cstdint>

#define NB 1024
#define NT 256
#define NE 300
#define LOG2E 1.4426950408889634f
#define INVL2E 0.6931471805599453f
#define NTH 512
#define RH 128        // rows per half
#define CH 16         // online-softmax chunk (registers)

// ---------------- static device precompute (no allocations allowed) ----------------
__device__ float g_M[NT * NT];       // M[t][f] = sum_e TE[e][t] * Wf[f][e]
__device__ float g_G2[NT * NT];      // (M M^T) * log2(e)   (symmetric)
__device__ float g_v2[NT];           // (M b_f) * log2(e)
__device__ float g_c2;               // (b_f . b_f) * log2(e)

__device__ __forceinline__ float fast_exp2(float x) {
    float y; asm("ex2.approx.f32 %0, %1;" : "=f"(y) : "f"(x)); return y;
}
__device__ __forceinline__ float fast_rcp(float x) {
    float y; asm("rcp.approx.f32 %0, %1;" : "=f"(y) : "f"(x)); return y;
}

// ---------------- k_M: tiled GEMM  M[t][f] = sum_e TE[e][t] * WF[f][e] ----------------
// grid (8,8), block (32,32). Coalesced loads, 33-stride smem (conflict-free).
__global__ void __launch_bounds__(1024) k_M(const float* __restrict__ te,
                                            const float* __restrict__ wf) {
    __shared__ float TEs[32][33];   // TEs[e_l][t_l]
    __shared__ float WFs[32][33];   // WFs[f_l][e_l]
    int tx = threadIdx.x, ty = threadIdx.y;
    int t0 = blockIdx.y * 32, f0 = blockIdx.x * 32;
    float acc = 0.f;
    for (int e0 = 0; e0 < NE; e0 += 32) {
        int e1 = e0 + ty;
        TEs[ty][tx] = (e1 < NE) ? te[e1 * NT + t0 + tx] : 0.f;          // coalesced in t
        int e2 = e0 + tx;
        WFs[ty][tx] = (e2 < NE) ? wf[(f0 + ty) * NE + e2] : 0.f;        // coalesced in e
        __syncthreads();
#pragma unroll
        for (int k = 0; k < 32; k++)
            acc = fmaf(TEs[k][ty], WFs[tx][k], acc);   // broadcast / conflict-free
        __syncthreads();
    }
    g_M[(t0 + ty) * NT + f0 + tx] = acc;
}

// ---------------- k_G: tiled GEMM  G2[i][j] = (sum_k M[i][k] M[j][k]) * log2e ----------
__global__ void __launch_bounds__(1024) k_G() {
    __shared__ float As[32][33];    // As[i_l][k_l]
    __shared__ float Bs[32][33];    // Bs[j_l][k_l]
    int tx = threadIdx.x, ty = threadIdx.y;
    int i0 = blockIdx.y * 32, j0 = blockIdx.x * 32;
    float acc = 0.f;
    for (int k0 = 0; k0 < NT; k0 += 32) {
        As[ty][tx] = g_M[(i0 + ty) * NT + k0 + tx];
        Bs[ty][tx] = g_M[(j0 + ty) * NT + k0 + tx];
        __syncthreads();
#pragma unroll
        for (int k = 0; k < 32; k++)
            acc = fmaf(As[ty][k], Bs[tx][k], acc);
        __syncthreads();
    }
    g_G2[(i0 + ty) * NT + j0 + tx] = acc * LOG2E;
}

// ---------------- k_v: v2 = (M b_f)*log2e, c2 = (b_f.b_f)*log2e ----------------
__global__ void k_v(const float* __restrict__ bf) {
    __shared__ float bsh[NT];
    int j = threadIdx.x;
    bsh[j] = bf[j];
    __syncthreads();
    const float* mj = g_M + j * NT;
    float a0 = 0.f, a1 = 0.f;
#pragma unroll 8
    for (int k = 0; k < NT; k += 2) {
        a0 = fmaf(mj[k], bsh[k], a0);
        a1 = fmaf(mj[k + 1], bsh[k + 1], a1);
    }
    g_v2[j] = (a0 + a1) * LOG2E;
    if (j == 0) {
        float c0 = 0.f;
        for (int k = 0; k < NT; k++) c0 = fmaf(bsh[k], bsh[k], c0);
        g_c2 = c0 * LOG2E;
    }
}

// ---------------- fused per-batch kernel (512 thr: column c, row-half h) -----------
// A2[r][c] = (w_c*r_r)*G2[r][c] + p2[r] + base_c   (log2 domain, G2 symmetric)
// Pass A: per-column online max/Z + y=G*r piggyback (no weight storage).
// Pass B: s_j = sum_c exp2(A2[j][c]-mx_c)*invZ_c, recomputed via G[c][j] (coalesced).
// Pass C: z = G*u. Quadratic-form cosine at the end.
__global__ void __launch_bounds__(NTH, 2) k_fused(const float* __restrict__ req,
                                                  const float* __restrict__ wsdl,
                                                  float* __restrict__ out) {
    __shared__ float rs[NT], p2[NT], wcs[NT], qc[NT], iZc[NT], ys[NT], us[NT];
    __shared__ float mh[2 * NT], Zh[2 * NT], yh[2 * NT], sh[2 * NT], zh[2 * NT];
    __shared__ float red[16 * 6];

    int tid = threadIdx.x;
    int c = tid & (NT - 1);
    int h = tid >> 8;
    int b = blockIdx.x;

    float w_c = wsdl[b * NT + c];
    float r_c = req[b * NT + c];
    float v2c = g_v2[c];
    if (h == 0) { rs[c] = r_c; p2[c] = r_c * v2c; }
    __syncthreads();
    float base = fmaf(w_c, v2c, g_c2);
    const float* Gc = g_G2 + c;
    int r0 = h * RH;

    // ---- pass A: online column max + Z + y2 over rows [r0, r0+RH) ----
    float m = -1e30f, Z = 0.f, y2 = 0.f;
#pragma unroll
    for (int k = 0; k < RH / CH; k++) {
        int rb = r0 + k * CH;
        float a[CH];
        float cm = -1e30f;
#pragma unroll
        for (int i = 0; i < CH; i++) {
            float g  = Gc[(rb + i) * NT];
            float rr = rs[rb + i];
            a[i] = fmaf(w_c * rr, g, p2[rb + i] + base);
            y2 = fmaf(g, rr, y2);
            cm = fmaxf(cm, a[i]);
        }
        float mn = fmaxf(m, cm);
        Z *= fast_exp2(m - mn);   // first chunk: 0 * 2^-huge = 0
        m = mn;
#pragma unroll
        for (int i = 0; i < CH; i++) Z += fast_exp2(a[i] - m);
    }
    mh[h * NT + c] = m; Zh[h * NT + c] = Z; yh[h * NT + c] = y2;
    __syncthreads();

    if (h == 0) {
        float m0 = mh[c], m1 = mh[NT + c];
        float mx = fmaxf(m0, m1);
        float Zc = Zh[c] * fast_exp2(m0 - mx) + Zh[NT + c] * fast_exp2(m1 - mx);
        iZc[c] = fast_rcp(Zc);
        qc[c]  = base - mx;
        wcs[c] = w_c;
        ys[c]  = yh[c] + yh[NT + c];
    }
    __syncthreads();

    // ---- pass B: s_j over columns [r0, r0+RH) using symmetry G[j][cc]=G[cc][j] ----
    {
        float p2j = r_c * v2c;   // p2[j], j == c
        float s = 0.f;
#pragma unroll 8
        for (int cc = r0; cc < r0 + RH; cc++) {
            float g = g_G2[cc * NT + c];                 // coalesced across warp
            float e = fast_exp2(fmaf(wcs[cc] * r_c, g, p2j + qc[cc]));
            s = fmaf(e, iZc[cc], s);
        }
        sh[h * NT + c] = s;
    }
    __syncthreads();
    float st = sh[c] + sh[NT + c];     // s_j, j == c
    float u  = st * r_c;
    if (h == 0) us[c] = u;
    __syncthreads();

    // ---- pass C: z = G*u partials over rows [r0, r0+RH) ----
    float z2 = 0.f;
#pragma unroll 16
    for (int r = r0; r < r0 + RH; r++)
        z2 = fmaf(Gc[r * NT], us[r], z2);
    zh[h * NT + c] = z2;
    __syncthreads();
    float z2t = zh[c] + zh[NT + c];
    float y2t = ys[c];

    // ---- reductions: T0=r.y T1=u.y T2=u.z T3=r.v2 T4=u.v2 T5=S ----
    float t0 = 0.f, t1 = 0.f, t2 = 0.f, t3 = 0.f, t4 = 0.f, t5 = 0.f;
    if (h == 0) {
        t0 = r_c * y2t; t1 = u * y2t; t2 = u * z2t;
        t3 = r_c * v2c; t4 = u * v2c; t5 = st;
    }
#pragma unroll
    for (int o = 16; o; o >>= 1) {
        t0 += __shfl_down_sync(0xffffffffu, t0, o);
        t1 += __shfl_down_sync(0xffffffffu, t1, o);
        t2 += __shfl_down_sync(0xffffffffu, t2, o);
        t3 += __shfl_down_sync(0xffffffffu, t3, o);
        t4 += __shfl_down_sync(0xffffffffu, t4, o);
        t5 += __shfl_down_sync(0xffffffffu, t5, o);
    }
    if ((tid & 31) == 0) {
        int w = tid >> 5;
        red[w * 6 + 0] = t0; red[w * 6 + 1] = t1; red[w * 6 + 2] = t2;
        red[w * 6 + 3] = t3; red[w * 6 + 4] = t4; red[w * 6 + 5] = t5;
    }
    __syncthreads();
    if (tid == 0) {
        float T0 = 0, T1 = 0, T2 = 0, T3 = 0, T4 = 0, S = 0;
#pragma unroll
        for (int w = 0; w < 16; w++) {
            T0 += red[w * 6 + 0]; T1 += red[w * 6 + 1]; T2 += red[w * 6 + 2];
            T3 += red[w * 6 + 3]; T4 += red[w * 6 + 4]; S  += red[w * 6 + 5];
        }
        float c_un = g_c2 * INVL2E;
        const float Tf = (float)NT;
        float num = (T1 + S * T3 + Tf * T4) * INVL2E + Tf * S * c_un;
        float n1s = (T0 + 2.0f * Tf * T3) * INVL2E + Tf * Tf * c_un;
        float n2s = (T2 + 2.0f * S * T4) * INVL2E + S * S * c_un;
        float denom = fmaxf(sqrtf(n1s) * sqrtf(n2s), 1e-8f * Tf * Tf);
        out[b] = 3.0f * num / denom;
    }
}

extern "C" void kernel_launch(void* const* d_in, const int* in_sizes, int n_in,
                              void* d_out, int out_size) {
    const float* req  = (const float*)d_in[0];   // [B,T]
    const float* wsdl = (const float*)d_in[1];   // [B,T]
    const float* te   = (const float*)d_in[2];   // [E,T]
    const float* wf   = (const float*)d_in[3];   // [T,E]
    const float* bf   = (const float*)d_in[4];   // [T]
    float* out = (float*)d_out;                  // [B]

    dim3 blk2(32, 32), grd2(8, 8);
    k_M<<<grd2, blk2>>>(te, wf);
    k_G<<<grd2, blk2>>>();
    k_v<<<1, NT>>>(bf);
    k_fused<<<NB, NTH>>>(req, wsdl, out);
}

// round 8
// speedup vs baseline: 5.9266x; 1.5128x over previous
#include <cuda_runtime.h>
#include <cuda_fp16.h>
#include <cstdint>

#define NB 1024
#define NT 256
#define NE 300
#define LOG2E 1.4426950408889634f
#define INVL2E 0.6931471805599453f
#define NTH 512
#define RH 128        // rows per half
#define CH 16         // online-softmax chunk (registers)

// ---------------- static device precompute (no allocations allowed) ----------------
__device__ float g_M[NT * NT];       // M[t][f] = sum_e TE[e][t] * Wf[f][e]
__device__ float g_G2[NT * NT];      // (M M^T) * log2(e)   (symmetric)
__device__ float g_v2[NT];           // (M b_f) * log2(e)
__device__ float g_c2;               // (b_f . b_f) * log2(e)

__device__ __forceinline__ float fast_exp2(float x) {
    float y; asm("ex2.approx.f32 %0, %1;" : "=f"(y) : "f"(x)); return y;
}
__device__ __forceinline__ float fast_lg2(float x) {
    float y; asm("lg2.approx.f32 %0, %1;" : "=f"(y) : "f"(x)); return y;
}

// ---------------- k_M: tiled GEMM, 256 thr, 4 outputs/thread --------------------
// M[t][f] = sum_e TE[e][t] * WF[f][e].  grid (8,8), block (32,8).
__global__ void __launch_bounds__(256) k_M(const float* __restrict__ te,
                                           const float* __restrict__ wf) {
    __shared__ float TEs[32][33];   // [e_l][t_l]
    __shared__ float WFs[32][33];   // [f_l][e_l]
    int tx = threadIdx.x, ty = threadIdx.y;     // tx: f_l, ty: 0..7
    int t0 = blockIdx.y * 32, f0 = blockIdx.x * 32;
    float acc[4] = {0.f, 0.f, 0.f, 0.f};
    for (int e0 = 0; e0 < NE; e0 += 32) {
#pragma unroll
        for (int q = 0; q < 4; q++) {
            int row = q * 8 + ty;
            int e1 = e0 + row;
            TEs[row][tx] = (e1 < NE) ? te[e1 * NT + t0 + tx] : 0.f;     // coalesced in t
            int e2 = e0 + tx;
            WFs[row][tx] = (e2 < NE) ? wf[(f0 + row) * NE + e2] : 0.f;  // coalesced in e
        }
        __syncthreads();
#pragma unroll
        for (int k = 0; k < 32; k++) {
            float bv = WFs[tx][k];
#pragma unroll
            for (int j = 0; j < 4; j++)
                acc[j] = fmaf(TEs[k][ty + 8 * j], bv, acc[j]);   // broadcast + lane load
        }
        __syncthreads();
    }
#pragma unroll
    for (int j = 0; j < 4; j++)
        g_M[(t0 + ty + 8 * j) * NT + f0 + tx] = acc[j];
}

// ---------------- k_Gv: G2 = (M M^T)*log2e (tiled, 4 out/thr) + v2 + c2 ------------
__global__ void __launch_bounds__(256) k_Gv(const float* __restrict__ bf) {
    __shared__ float As[32][33];    // [i_l][k_l]
    __shared__ float Bs[32][33];    // [j_l][k_l]
    __shared__ float bshf[NT];
    int tx = threadIdx.x, ty = threadIdx.y;
    int lid = ty * 32 + tx;
    int i0 = blockIdx.y * 32, j0 = blockIdx.x * 32;
    bshf[lid] = bf[lid];            // 256 threads exactly cover NT
    float acc[4] = {0.f, 0.f, 0.f, 0.f};
    float vacc = 0.f;
    for (int k0 = 0; k0 < NT; k0 += 32) {
#pragma unroll
        for (int q = 0; q < 4; q++) {
            int row = q * 8 + ty;
            As[row][tx] = g_M[(i0 + row) * NT + k0 + tx];
            Bs[row][tx] = g_M[(j0 + row) * NT + k0 + tx];
        }
        __syncthreads();
#pragma unroll
        for (int k = 0; k < 32; k++) {
            float bv = Bs[tx][k];
#pragma unroll
            for (int j = 0; j < 4; j++)
                acc[j] = fmaf(As[ty + 8 * j][k], bv, acc[j]);
        }
        if (blockIdx.y == 0 && ty == 0) {
#pragma unroll
            for (int k = 0; k < 32; k++)
                vacc = fmaf(Bs[tx][k], bshf[k0 + k], vacc);
        }
        __syncthreads();
    }
#pragma unroll
    for (int j = 0; j < 4; j++)
        g_G2[(i0 + ty + 8 * j) * NT + j0 + tx] = acc[j] * LOG2E;
    if (blockIdx.y == 0 && ty == 0) {
        g_v2[j0 + tx] = vacc * LOG2E;
        if (blockIdx.x == 0 && tx == 0) {
            float c0 = 0.f;
            for (int k = 0; k < NT; k++) c0 = fmaf(bshf[k], bshf[k], c0);
            g_c2 = c0 * LOG2E;
        }
    }
}

// ---------------- fused per-batch kernel (512 thr: column c, row-half h) -----------
// log2-domain logits with per-column constant (base) dropped — it cancels in the
// column softmax:  a'[r][c] = (w_c*r_r)*G2[r][c] + p2[r]
// Pass A: online column max/Z + y=G*r piggyback.
// Pass B: s_j = sum_c 2^( (w_c*r_j)*G[c][j] + qcz_c ) * 2^{p2j}, with
//         qcz_c = -mx_c - lg2(Z_c)  (mx, logZ, p2j all folded out of the loop).
// Pass C: z = G*u. Quadratic-form cosine at the end.
__global__ void __launch_bounds__(NTH, 2) k_fused(const float* __restrict__ req,
                                                  const float* __restrict__ wsdl,
                                                  float* __restrict__ out) {
    __shared__ float2 rp[NT];       // (r, r*v2)
    __shared__ float2 bq[NT];       // (w_c, qcz)
    __shared__ float us[NT], ys[NT];
    __shared__ float mh[2 * NT], Zh[2 * NT], yh[2 * NT], sh[2 * NT], zh[2 * NT];
    __shared__ float red[16 * 6];

    int tid = threadIdx.x;
    int c = tid & (NT - 1);
    int h = tid >> 8;
    int b = blockIdx.x;

    float w_c = wsdl[b * NT + c];
    float r_c = req[b * NT + c];
    float v2c = g_v2[c];
    float p2j = r_c * v2c;
    if (h == 0) rp[c] = make_float2(r_c, p2j);
    __syncthreads();
    const float* Gc = g_G2 + c;
    int r0 = h * RH;

    // ---- pass A: online column max + Z + y2 over rows [r0, r0+RH) ----
    float m = -1e30f, Z = 0.f, y2 = 0.f;
#pragma unroll
    for (int k = 0; k < RH / CH; k++) {
        int rb = r0 + k * CH;
        float a[CH];
        float cm = -1e30f;
#pragma unroll
        for (int i = 0; i < CH; i++) {
            float g = Gc[(rb + i) * NT];
            float2 q = rp[rb + i];
            a[i] = fmaf(w_c * q.x, g, q.y);
            y2 = fmaf(g, q.x, y2);
            cm = fmaxf(cm, a[i]);
        }
        float mn = fmaxf(m, cm);
        Z *= fast_exp2(m - mn);       // first chunk: 0 * 2^-huge = 0
        m = mn;
#pragma unroll
        for (int i = 0; i < CH; i++) Z += fast_exp2(a[i] - m);
    }
    mh[h * NT + c] = m; Zh[h * NT + c] = Z; yh[h * NT + c] = y2;
    __syncthreads();

    if (h == 0) {
        float m0 = mh[c], m1 = mh[NT + c];
        float mx = fmaxf(m0, m1);
        float Zc = Zh[c] * fast_exp2(m0 - mx) + Zh[NT + c] * fast_exp2(m1 - mx);
        bq[c] = make_float2(w_c, -mx - fast_lg2(Zc));
        ys[c] = yh[c] + yh[NT + c];
    }
    __syncthreads();

    // ---- pass B: s_j over columns [r0, r0+RH) via symmetry G[j][cc]=G[cc][j] ----
    {
        float s = 0.f;
#pragma unroll 16
        for (int cc = r0; cc < r0 + RH; cc++) {
            float g = Gc[cc * NT];                // coalesced across warp (lane = j)
            float2 t = bq[cc];
            s += fast_exp2(fmaf(t.x * r_c, g, t.y));
        }
        sh[h * NT + c] = s * fast_exp2(p2j);
    }
    __syncthreads();
    float st = sh[c] + sh[NT + c];     // s_j, j == c
    float u  = st * r_c;
    if (h == 0) us[c] = u;
    __syncthreads();

    // ---- pass C: z = G*u partials over rows [r0, r0+RH) ----
    float z2 = 0.f;
#pragma unroll 16
    for (int r = r0; r < r0 + RH; r++)
        z2 = fmaf(Gc[r * NT], us[r], z2);
    zh[h * NT + c] = z2;
    __syncthreads();
    float z2t = zh[c] + zh[NT + c];
    float y2t = ys[c];

    // ---- reductions: T0=r.y T1=u.y T2=u.z T3=r.v2 T4=u.v2 T5=S ----
    float t0 = 0.f, t1 = 0.f, t2 = 0.f, t3 = 0.f, t4 = 0.f, t5 = 0.f;
    if (h == 0) {
        t0 = r_c * y2t; t1 = u * y2t; t2 = u * z2t;
        t3 = r_c * v2c; t4 = u * v2c; t5 = st;
    }
#pragma unroll
    for (int o = 16; o; o >>= 1) {
        t0 += __shfl_down_sync(0xffffffffu, t0, o);
        t1 += __shfl_down_sync(0xffffffffu, t1, o);
        t2 += __shfl_down_sync(0xffffffffu, t2, o);
        t3 += __shfl_down_sync(0xffffffffu, t3, o);
        t4 += __shfl_down_sync(0xffffffffu, t4, o);
        t5 += __shfl_down_sync(0xffffffffu, t5, o);
    }
    if ((tid & 31) == 0) {
        int w = tid >> 5;
        red[w * 6 + 0] = t0; red[w * 6 + 1] = t1; red[w * 6 + 2] = t2;
        red[w * 6 + 3] = t3; red[w * 6 + 4] = t4; red[w * 6 + 5] = t5;
    }
    __syncthreads();
    if (tid == 0) {
        float T0 = 0, T1 = 0, T2 = 0, T3 = 0, T4 = 0, S = 0;
#pragma unroll
        for (int w = 0; w < 16; w++) {
            T0 += red[w * 6 + 0]; T1 += red[w * 6 + 1]; T2 += red[w * 6 + 2];
            T3 += red[w * 6 + 3]; T4 += red[w * 6 + 4]; S  += red[w * 6 + 5];
        }
        float c_un = g_c2 * INVL2E;
        const float Tf = (float)NT;
        float num = (T1 + S * T3 + Tf * T4) * INVL2E + Tf * S * c_un;
        float n1s = (T0 + 2.0f * Tf * T3) * INVL2E + Tf * Tf * c_un;
        float n2s = (T2 + 2.0f * S * T4) * INVL2E + S * S * c_un;
        float denom = fmaxf(sqrtf(n1s) * sqrtf(n2s), 1e-8f * Tf * Tf);
        out[b] = 3.0f * num / denom;
    }
}

extern "C" void kernel_launch(void* const* d_in, const int* in_sizes, int n_in,
                              void* d_out, int out_size) {
    const float* req  = (const float*)d_in[0];   // [B,T]
    const float* wsdl = (const float*)d_in[1];   // [B,T]
    const float* te   = (const float*)d_in[2];   // [E,T]
    const float* wf   = (const float*)d_in[3];   // [T,E]
    const float* bf   = (const float*)d_in[4];   // [T]
    float* out = (float*)d_out;                  // [B]

    dim3 blk(32, 8), grd(8, 8);
    k_M<<<grd, blk>>>(te, wf);
    k_Gv<<<grd, blk>>>(bf);
    k_fused<<<NB, NTH>>>(req, wsdl, out);
}

// round 9
// speedup vs baseline: 6.8759x; 1.1602x over previous
#include <cuda_runtime.h>
#include <cuda_fp16.h>
#include <cstdint>

#define NB 1024
#define NT 256
#define NE 300
#define LOG2E 1.4426950408889634f
#define INVL2E 0.6931471805599453f
#define NTH 512
#define RH4 64        // rows per quarter
#define CH 8          // online-softmax chunk (registers per column)

// ---------------- static device precompute (no allocations allowed) ----------------
__device__ float g_M[NT * NT];       // M[t][f] = sum_e TE[e][t] * Wf[f][e]
__device__ float g_G2[NT * NT];      // (M M^T) * log2(e)   (symmetric)
__device__ float g_v2[NT];           // (M b_f) * log2(e)
__device__ float g_c2;               // (b_f . b_f) * log2(e)

__device__ __forceinline__ float fast_exp2(float x) {
    float y; asm("ex2.approx.f32 %0, %1;" : "=f"(y) : "f"(x)); return y;
}
__device__ __forceinline__ float fast_lg2(float x) {
    float y; asm("lg2.approx.f32 %0, %1;" : "=f"(y) : "f"(x)); return y;
}

// ---------------- k_M: tiled GEMM, double-buffered smem --------------------------
// M[t][f] = sum_e TE[e][t] * WF[f][e].  grid (8,8), block (32,8), 4 out/thread.
__global__ void __launch_bounds__(256) k_M(const float* __restrict__ te,
                                           const float* __restrict__ wf) {
    __shared__ float TEs[2][32][33];   // [buf][e_l][t_l]
    __shared__ float WFs[2][32][33];   // [buf][f_l][e_l]
    int tx = threadIdx.x, ty = threadIdx.y;
    int t0 = blockIdx.y * 32, f0 = blockIdx.x * 32;
    const int NTILE = (NE + 31) / 32;  // 10

    float pTE[4], pWF[4];
    // preload tile 0
#pragma unroll
    for (int q = 0; q < 4; q++) {
        int row = q * 8 + ty;
        pTE[q] = (row < NE) ? te[row * NT + t0 + tx] : 0.f;
        pWF[q] = (tx < NE) ? wf[(f0 + row) * NE + tx] : 0.f;
    }
#pragma unroll
    for (int q = 0; q < 4; q++) {
        int row = q * 8 + ty;
        TEs[0][row][tx] = pTE[q];
        WFs[0][row][tx] = pWF[q];
    }
    __syncthreads();

    float acc[4] = {0.f, 0.f, 0.f, 0.f};
    for (int it = 0; it < NTILE; it++) {
        int cur = it & 1;
        int e0n = (it + 1) * 32;
        if (it + 1 < NTILE) {
#pragma unroll
            for (int q = 0; q < 4; q++) {
                int row = q * 8 + ty;
                int e1 = e0n + row;
                pTE[q] = (e1 < NE) ? te[e1 * NT + t0 + tx] : 0.f;
                int e2 = e0n + tx;
                pWF[q] = (e2 < NE) ? wf[(f0 + row) * NE + e2] : 0.f;
            }
        }
#pragma unroll
        for (int k = 0; k < 32; k++) {
            float bv = WFs[cur][tx][k];
#pragma unroll
            for (int j = 0; j < 4; j++)
                acc[j] = fmaf(TEs[cur][k][ty + 8 * j], bv, acc[j]);
        }
        if (it + 1 < NTILE) {
#pragma unroll
            for (int q = 0; q < 4; q++) {
                int row = q * 8 + ty;
                TEs[cur ^ 1][row][tx] = pTE[q];
                WFs[cur ^ 1][row][tx] = pWF[q];
            }
        }
        __syncthreads();
    }
#pragma unroll
    for (int j = 0; j < 4; j++)
        g_M[(t0 + ty + 8 * j) * NT + f0 + tx] = acc[j];
}

// ---------------- k_Gv: G2 = (M M^T)*log2e, double-buffered; + v2 + c2 ------------
__global__ void __launch_bounds__(256) k_Gv(const float* __restrict__ bf) {
    __shared__ float As[2][32][33];
    __shared__ float Bs[2][32][33];
    __shared__ float bshf[NT];
    int tx = threadIdx.x, ty = threadIdx.y;
    int lid = ty * 32 + tx;
    int i0 = blockIdx.y * 32, j0 = blockIdx.x * 32;
    bshf[lid] = bf[lid];

    float pA[4], pB[4];
#pragma unroll
    for (int q = 0; q < 4; q++) {
        int row = q * 8 + ty;
        pA[q] = g_M[(i0 + row) * NT + tx];
        pB[q] = g_M[(j0 + row) * NT + tx];
    }
#pragma unroll
    for (int q = 0; q < 4; q++) {
        int row = q * 8 + ty;
        As[0][row][tx] = pA[q];
        Bs[0][row][tx] = pB[q];
    }
    __syncthreads();

    float acc[4] = {0.f, 0.f, 0.f, 0.f};
    float vacc = 0.f;
    for (int it = 0; it < 8; it++) {
        int cur = it & 1;
        int k0n = (it + 1) * 32;
        if (it + 1 < 8) {
#pragma unroll
            for (int q = 0; q < 4; q++) {
                int row = q * 8 + ty;
                pA[q] = g_M[(i0 + row) * NT + k0n + tx];
                pB[q] = g_M[(j0 + row) * NT + k0n + tx];
            }
        }
#pragma unroll
        for (int k = 0; k < 32; k++) {
            float bv = Bs[cur][tx][k];
#pragma unroll
            for (int j = 0; j < 4; j++)
                acc[j] = fmaf(As[cur][ty + 8 * j][k], bv, acc[j]);
        }
        if (blockIdx.y == 0 && ty == 0) {
#pragma unroll
            for (int k = 0; k < 32; k++)
                vacc = fmaf(Bs[cur][tx][k], bshf[it * 32 + k], vacc);
        }
        if (it + 1 < 8) {
#pragma unroll
            for (int q = 0; q < 4; q++) {
                int row = q * 8 + ty;
                As[cur ^ 1][row][tx] = pA[q];
                Bs[cur ^ 1][row][tx] = pB[q];
            }
        }
        __syncthreads();
    }
#pragma unroll
    for (int j = 0; j < 4; j++)
        g_G2[(i0 + ty + 8 * j) * NT + j0 + tx] = acc[j] * LOG2E;
    if (blockIdx.y == 0 && ty == 0) {
        g_v2[j0 + tx] = vacc * LOG2E;
        if (blockIdx.x == 0 && tx == 0) {
            float c0 = 0.f;
            for (int k = 0; k < NT; k++) c0 = fmaf(bshf[k], bshf[k], c0);
            g_c2 = c0 * LOG2E;
        }
    }
}

// ---------------- fused per-batch kernel (512 thr: 128 col-pairs x 4 row-quarters) --
// a'[r][c] = (w_c*r_r)*G2[r][c] + p2[r]   (log2 domain; per-column const cancels)
// Thread owns columns c0=2cp, c1=2cp+1 (LDG.64 on G2) and rows [64h, 64h+64).
// Pass A: online column max/Z + y=G*r piggyback. Pass B: s_j recomputed via
// symmetry, qcz_c = -mx_c - lg2(Z_c). Pass C: z=G*u. Quadratic-form cosine.
__global__ void __launch_bounds__(NTH, 2) k_fused(const float* __restrict__ req,
                                                  const float* __restrict__ wsdl,
                                                  float* __restrict__ out) {
    __shared__ float2 rp[NT];          // (r, r*v2) per row
    __shared__ float2 bq[NT];          // (w_c, qcz_c) per column
    __shared__ float  us[NT];
    __shared__ float2 mh2[4 * 128], Zh2[4 * 128], yh2[4 * 128];
    __shared__ float2 sh2[4 * 128], zh2[4 * 128];
    __shared__ float red[16 * 6];

    int tid = threadIdx.x;
    int cp = tid & 127;
    int h = tid >> 7;
    int b = blockIdx.x;

    float2 rr = ((const float2*)req)[b * 128 + cp];
    float2 ww = ((const float2*)wsdl)[b * 128 + cp];
    float2 vv = ((const float2*)g_v2)[cp];
    float p20 = rr.x * vv.x, p21 = rr.y * vv.y;
    if (h == 0) {
        rp[2 * cp]     = make_float2(rr.x, p20);
        rp[2 * cp + 1] = make_float2(rr.y, p21);
    }
    __syncthreads();

    const float2* G2v = (const float2*)g_G2;   // row r: G2v[r*128 + cp]
    int rbase = h * RH4;

    // ---- pass A: online column max + Z + y over rows [rbase, rbase+64) ----
    float m0 = -1e30f, m1 = -1e30f, Z0 = 0.f, Z1 = 0.f, y0 = 0.f, y1 = 0.f;
#pragma unroll
    for (int k = 0; k < RH4 / CH; k++) {
        float a0[CH], a1[CH];
        float cm0 = -1e30f, cm1 = -1e30f;
#pragma unroll
        for (int i = 0; i < CH; i++) {
            int r = rbase + k * CH + i;
            float2 g = G2v[r * 128 + cp];
            float2 q = rp[r];                      // broadcast
            a0[i] = fmaf(ww.x * q.x, g.x, q.y);
            a1[i] = fmaf(ww.y * q.x, g.y, q.y);
            y0 = fmaf(g.x, q.x, y0);
            y1 = fmaf(g.y, q.x, y1);
            cm0 = fmaxf(cm0, a0[i]);
            cm1 = fmaxf(cm1, a1[i]);
        }
        float mn0 = fmaxf(m0, cm0), mn1 = fmaxf(m1, cm1);
        Z0 *= fast_exp2(m0 - mn0);   // first chunk: 0 * 2^-huge = 0
        Z1 *= fast_exp2(m1 - mn1);
        m0 = mn0; m1 = mn1;
#pragma unroll
        for (int i = 0; i < CH; i++) {
            Z0 += fast_exp2(a0[i] - m0);
            Z1 += fast_exp2(a1[i] - m1);
        }
    }
    mh2[h * 128 + cp] = make_float2(m0, m1);
    Zh2[h * 128 + cp] = make_float2(Z0, Z1);
    yh2[h * 128 + cp] = make_float2(y0, y1);
    __syncthreads();

    // ---- combine column stats (h==0) -> bq ----
    if (h == 0) {
        float2 ma = mh2[cp], mb = mh2[128 + cp], mc = mh2[256 + cp], md = mh2[384 + cp];
        float mx0 = fmaxf(fmaxf(ma.x, mb.x), fmaxf(mc.x, md.x));
        float mx1 = fmaxf(fmaxf(ma.y, mb.y), fmaxf(mc.y, md.y));
        float2 za = Zh2[cp], zb = Zh2[128 + cp], zc = Zh2[256 + cp], zd = Zh2[384 + cp];
        float Zt0 = za.x * fast_exp2(ma.x - mx0) + zb.x * fast_exp2(mb.x - mx0)
                  + zc.x * fast_exp2(mc.x - mx0) + zd.x * fast_exp2(md.x - mx0);
        float Zt1 = za.y * fast_exp2(ma.y - mx1) + zb.y * fast_exp2(mb.y - mx1)
                  + zc.y * fast_exp2(mc.y - mx1) + zd.y * fast_exp2(md.y - mx1);
        bq[2 * cp]     = make_float2(ww.x, -mx0 - fast_lg2(Zt0));
        bq[2 * cp + 1] = make_float2(ww.y, -mx1 - fast_lg2(Zt1));
    }
    __syncthreads();

    // ---- pass B: s_j over columns cc in [rbase, rbase+64), j = c0,c1 ----
    {
        float s0 = 0.f, s1 = 0.f;
#pragma unroll 8
        for (int cc = rbase; cc < rbase + RH4; cc++) {
            float2 g = G2v[cc * 128 + cp];         // G2[cc][c0], G2[cc][c1]
            float2 t = bq[cc];                     // broadcast
            s0 += fast_exp2(fmaf(t.x * rr.x, g.x, t.y));
            s1 += fast_exp2(fmaf(t.x * rr.y, g.y, t.y));
        }
        sh2[h * 128 + cp] = make_float2(s0, s1);
    }
    __syncthreads();

    // ---- u (h==0 only) ----
    float st0 = 0.f, st1 = 0.f, u0 = 0.f, u1 = 0.f;
    if (h == 0) {
        float2 sa = sh2[cp], sb = sh2[128 + cp], sc = sh2[256 + cp], sd = sh2[384 + cp];
        st0 = ((sa.x + sb.x) + (sc.x + sd.x)) * fast_exp2(p20);
        st1 = ((sa.y + sb.y) + (sc.y + sd.y)) * fast_exp2(p21);
        u0 = st0 * rr.x;
        u1 = st1 * rr.y;
        us[2 * cp] = u0;
        us[2 * cp + 1] = u1;
    }
    __syncthreads();

    // ---- pass C: z = G*u partials ----
    {
        float z0 = 0.f, z1 = 0.f;
#pragma unroll 8
        for (int r = rbase; r < rbase + RH4; r++) {
            float2 g = G2v[r * 128 + cp];
            float uu = us[r];                      // broadcast
            z0 = fmaf(g.x, uu, z0);
            z1 = fmaf(g.y, uu, z1);
        }
        zh2[h * 128 + cp] = make_float2(z0, z1);
    }
    __syncthreads();

    // ---- reductions (h==0 contributes): T0=r.y T1=u.y T2=u.z T3=r.v T4=u.v T5=S --
    float t0 = 0.f, t1 = 0.f, t2 = 0.f, t3 = 0.f, t4 = 0.f, t5 = 0.f;
    if (h == 0) {
        float2 ya = yh2[cp], yb = yh2[128 + cp], yc = yh2[256 + cp], yd = yh2[384 + cp];
        float y0t = (ya.x + yb.x) + (yc.x + yd.x);
        float y1t = (ya.y + yb.y) + (yc.y + yd.y);
        float2 za = zh2[cp], zb = zh2[128 + cp], zc = zh2[256 + cp], zd = zh2[384 + cp];
        float z0t = (za.x + zb.x) + (zc.x + zd.x);
        float z1t = (za.y + zb.y) + (zc.y + zd.y);
        t0 = rr.x * y0t + rr.y * y1t;
        t1 = u0 * y0t + u1 * y1t;
        t2 = u0 * z0t + u1 * z1t;
        t3 = rr.x * vv.x + rr.y * vv.y;
        t4 = u0 * vv.x + u1 * vv.y;
        t5 = st0 + st1;
    }
#pragma unroll
    for (int o = 16; o; o >>= 1) {
        t0 += __shfl_down_sync(0xffffffffu, t0, o);
        t1 += __shfl_down_sync(0xffffffffu, t1, o);
        t2 += __shfl_down_sync(0xffffffffu, t2, o);
        t3 += __shfl_down_sync(0xffffffffu, t3, o);
        t4 += __shfl_down_sync(0xffffffffu, t4, o);
        t5 += __shfl_down_sync(0xffffffffu, t5, o);
    }
    if ((tid & 31) == 0) {
        int w = tid >> 5;
        red[w * 6 + 0] = t0; red[w * 6 + 1] = t1; red[w * 6 + 2] = t2;
        red[w * 6 + 3] = t3; red[w * 6 + 4] = t4; red[w * 6 + 5] = t5;
    }
    __syncthreads();
    if (tid == 0) {
        float T0 = 0, T1 = 0, T2 = 0, T3 = 0, T4 = 0, S = 0;
#pragma unroll
        for (int w = 0; w < 4; w++) {             // only warps 0-3 contribute (h==0)
            T0 += red[w * 6 + 0]; T1 += red[w * 6 + 1]; T2 += red[w * 6 + 2];
            T3 += red[w * 6 + 3]; T4 += red[w * 6 + 4]; S  += red[w * 6 + 5];
        }
        float c_un = g_c2 * INVL2E;
        const float Tf = (float)NT;
        float num = (T1 + S * T3 + Tf * T4) * INVL2E + Tf * S * c_un;
        float n1s = (T0 + 2.0f * Tf * T3) * INVL2E + Tf * Tf * c_un;
        float n2s = (T2 + 2.0f * S * T4) * INVL2E + S * S * c_un;
        float denom = fmaxf(sqrtf(n1s) * sqrtf(n2s), 1e-8f * Tf * Tf);
        out[b] = 3.0f * num / denom;
    }
}

extern "C" void kernel_launch(void* const* d_in, const int* in_sizes, int n_in,
                              void* d_out, int out_size) {
    const float* req  = (const float*)d_in[0];   // [B,T]
    const float* wsdl = (const float*)d_in[1];   // [B,T]
    const float* te   = (const float*)d_in[2];   // [E,T]
    const float* wf   = (const float*)d_in[3];   // [T,E]
    const float* bf   = (const float*)d_in[4];   // [T]
    float* out = (float*)d_out;                  // [B]

    dim3 blk(32, 8), grd(8, 8);
    k_M<<<grd, blk>>>(te, wf);
    k_Gv<<<grd, blk>>>(bf);
    k_fused<<<NB, NTH>>>(req, wsdl, out);
}

// round 10
// speedup vs baseline: 7.0991x; 1.0325x over previous
#include <cuda_runtime.h>
#include <cuda_fp16.h>
#include <cstdint>

#define NB 1024
#define NT 256
#define NE 300
#define LOG2E 1.4426950408889634f
#define INVL2E 0.6931471805599453f
#define NTH 512
#define RH4 64        // rows per quarter
#define CH 8          // online-softmax chunk (registers per column)

// ---------------- static device precompute (no allocations allowed) ----------------
__device__ float g_M[NT * NT];       // M[t][f] = sum_e TE[e][t] * Wf[f][e]
__device__ float g_G2[NT * NT];      // (M M^T) * log2(e)   (symmetric)
__device__ float g_v2[NT];           // (M b_f) * log2(e)
__device__ float g_c2;               // (b_f . b_f) * log2(e)

__device__ __forceinline__ float fast_exp2(float x) {
    float y; asm("ex2.approx.f32 %0, %1;" : "=f"(y) : "f"(x)); return y;
}
__device__ __forceinline__ float fast_lg2(float x) {
    float y; asm("lg2.approx.f32 %0, %1;" : "=f"(y) : "f"(x)); return y;
}

// ---------------- k_M: 16x16 tiles, grid 256 (2 CTAs/SM), double-buffered ---------
// M[t][f] = sum_e TE[e][t] * WF[f][e].  256 threads, 1 output each.
__global__ void __launch_bounds__(256) k_M(const float* __restrict__ te,
                                           const float* __restrict__ wf) {
    __shared__ float TEs[2][32][17];   // [buf][e_l][t_l]
    __shared__ float WFs[2][16][33];   // [buf][f_l][e_l]
    int lid = threadIdx.x;
    int tx = lid & 15;                 // f_l
    int ty = lid >> 4;                 // t_l
    int t0 = blockIdx.y * 16, f0 = blockIdx.x * 16;
    int te_el = lid >> 4, te_tl = lid & 15;   // TE load map (2 elems/thread)
    int wf_el = lid & 31, wf_fl = lid >> 5;   // WF load map (2 elems/thread)
    const int NTILE = (NE + 31) / 32;         // 10

    float pT0, pT1, pW0, pW1;
    {
        int e1 = te_el;
        pT0 = (e1 < NE) ? te[e1 * NT + t0 + te_tl] : 0.f;
        int e2 = e1 + 16;
        pT1 = (e2 < NE) ? te[e2 * NT + t0 + te_tl] : 0.f;
        int e = wf_el;
        pW0 = (e < NE) ? wf[(f0 + wf_fl) * NE + e] : 0.f;
        pW1 = (e < NE) ? wf[(f0 + wf_fl + 8) * NE + e] : 0.f;
    }
    TEs[0][te_el][te_tl] = pT0; TEs[0][te_el + 16][te_tl] = pT1;
    WFs[0][wf_fl][wf_el] = pW0; WFs[0][wf_fl + 8][wf_el] = pW1;
    __syncthreads();

    float acc = 0.f;
    for (int it = 0; it < NTILE; it++) {
        int cur = it & 1;
        if (it + 1 < NTILE) {
            int e0 = (it + 1) * 32;
            int e1 = e0 + te_el;
            pT0 = (e1 < NE) ? te[e1 * NT + t0 + te_tl] : 0.f;
            int e2 = e1 + 16;
            pT1 = (e2 < NE) ? te[e2 * NT + t0 + te_tl] : 0.f;
            int e = e0 + wf_el;
            pW0 = (e < NE) ? wf[(f0 + wf_fl) * NE + e] : 0.f;
            pW1 = (e < NE) ? wf[(f0 + wf_fl + 8) * NE + e] : 0.f;
        }
#pragma unroll
        for (int k = 0; k < 32; k++)
            acc = fmaf(TEs[cur][k][ty], WFs[cur][tx][k], acc);
        if (it + 1 < NTILE) {
            TEs[cur ^ 1][te_el][te_tl] = pT0; TEs[cur ^ 1][te_el + 16][te_tl] = pT1;
            WFs[cur ^ 1][wf_fl][wf_el] = pW0; WFs[cur ^ 1][wf_fl + 8][wf_el] = pW1;
        }
        __syncthreads();
    }
    g_M[(t0 + ty) * NT + f0 + tx] = acc;
}

// ---------------- k_Gv: 16x16 tiles, grid 256, double-buffered; + v2 + c2 ---------
// G2[i][j] = (sum_k M[i][k] M[j][k]) * log2e
__global__ void __launch_bounds__(256) k_Gv(const float* __restrict__ bf) {
    __shared__ float As[2][32][17];    // [buf][k_l][i_l]
    __shared__ float Bs[2][16][33];    // [buf][j_l][k_l]
    __shared__ float bshf[NT];
    int lid = threadIdx.x;
    int tx = lid & 15;                 // j_l
    int ty = lid >> 4;                 // i_l
    int i0 = blockIdx.y * 16, j0 = blockIdx.x * 16;
    int kl = lid & 31, hl = lid >> 5;  // load map: 2 elems each for A and B
    bshf[lid] = bf[lid];

    float pA0, pA1, pB0, pB1;
    pA0 = g_M[(i0 + hl) * NT + kl];
    pA1 = g_M[(i0 + hl + 8) * NT + kl];
    pB0 = g_M[(j0 + hl) * NT + kl];
    pB1 = g_M[(j0 + hl + 8) * NT + kl];
    As[0][kl][hl] = pA0; As[0][kl][hl + 8] = pA1;
    Bs[0][hl][kl] = pB0; Bs[0][hl + 8][kl] = pB1;
    __syncthreads();

    float acc = 0.f, vacc = 0.f;
    for (int it = 0; it < 8; it++) {
        int cur = it & 1;
        if (it + 1 < 8) {
            int k0 = (it + 1) * 32;
            pA0 = g_M[(i0 + hl) * NT + k0 + kl];
            pA1 = g_M[(i0 + hl + 8) * NT + k0 + kl];
            pB0 = g_M[(j0 + hl) * NT + k0 + kl];
            pB1 = g_M[(j0 + hl + 8) * NT + k0 + kl];
        }
#pragma unroll
        for (int k = 0; k < 32; k++)
            acc = fmaf(As[cur][k][ty], Bs[cur][tx][k], acc);
        if (blockIdx.y == 0 && ty == 0) {
#pragma unroll
            for (int k = 0; k < 32; k++)
                vacc = fmaf(Bs[cur][tx][k], bshf[it * 32 + k], vacc);
        }
        if (it + 1 < 8) {
            As[cur ^ 1][kl][hl] = pA0; As[cur ^ 1][kl][hl + 8] = pA1;
            Bs[cur ^ 1][hl][kl] = pB0; Bs[cur ^ 1][hl + 8][kl] = pB1;
        }
        __syncthreads();
    }
    g_G2[(i0 + ty) * NT + j0 + tx] = acc * LOG2E;
    if (blockIdx.y == 0 && ty == 0) {
        g_v2[j0 + tx] = vacc * LOG2E;
        if (blockIdx.x == 0 && tx == 0) {
            float c0 = 0.f;
            for (int k = 0; k < NT; k++) c0 = fmaf(bshf[k], bshf[k], c0);
            g_c2 = c0 * LOG2E;
        }
    }
}

// ---------------- fused per-batch kernel (512 thr: 128 col-pairs x 4 row-quarters) --
// a'[r][c] = (w_c*r_r)*G2[r][c] + p2[r]   (log2 domain; per-column const cancels)
// Thread owns columns c0=2cp, c1=2cp+1 (LDG.64 on G2) and rows [64h, 64h+64).
// Pass A: online column max/Z + y=G*r piggyback. Pass B: s_j recomputed via
// symmetry, qcz_c = -mx_c - lg2(Z_c). Pass C: z=G*u. Quadratic-form cosine.
__global__ void __launch_bounds__(NTH, 2) k_fused(const float* __restrict__ req,
                                                  const float* __restrict__ wsdl,
                                                  float* __restrict__ out) {
    __shared__ float2 rp[NT];          // (r, r*v2) per row
    __shared__ float2 bq[NT];          // (w_c, qcz_c) per column
    __shared__ float  us[NT];
    __shared__ float2 mh2[4 * 128], Zh2[4 * 128], yh2[4 * 128];
    __shared__ float2 sh2[4 * 128], zh2[4 * 128];
    __shared__ float red[16 * 6];

    int tid = threadIdx.x;
    int cp = tid & 127;
    int h = tid >> 7;
    int b = blockIdx.x;

    float2 rr = ((const float2*)req)[b * 128 + cp];
    float2 ww = ((const float2*)wsdl)[b * 128 + cp];
    float2 vv = ((const float2*)g_v2)[cp];
    float p20 = rr.x * vv.x, p21 = rr.y * vv.y;
    if (h == 0) {
        rp[2 * cp]     = make_float2(rr.x, p20);
        rp[2 * cp + 1] = make_float2(rr.y, p21);
    }
    __syncthreads();

    const float2* G2v = (const float2*)g_G2;   // row r: G2v[r*128 + cp]
    int rbase = h * RH4;

    // ---- pass A: online column max + Z + y over rows [rbase, rbase+64) ----
    float m0 = -1e30f, m1 = -1e30f, Z0 = 0.f, Z1 = 0.f, y0 = 0.f, y1 = 0.f;
#pragma unroll
    for (int k = 0; k < RH4 / CH; k++) {
        float a0[CH], a1[CH];
        float cm0 = -1e30f, cm1 = -1e30f;
#pragma unroll
        for (int i = 0; i < CH; i++) {
            int r = rbase + k * CH + i;
            float2 g = G2v[r * 128 + cp];
            float2 q = rp[r];                      // broadcast
            a0[i] = fmaf(ww.x * q.x, g.x, q.y);
            a1[i] = fmaf(ww.y * q.x, g.y, q.y);
            y0 = fmaf(g.x, q.x, y0);
            y1 = fmaf(g.y, q.x, y1);
            cm0 = fmaxf(cm0, a0[i]);
            cm1 = fmaxf(cm1, a1[i]);
        }
        float mn0 = fmaxf(m0, cm0), mn1 = fmaxf(m1, cm1);
        Z0 *= fast_exp2(m0 - mn0);   // first chunk: 0 * 2^-huge = 0
        Z1 *= fast_exp2(m1 - mn1);
        m0 = mn0; m1 = mn1;
#pragma unroll
        for (int i = 0; i < CH; i++) {
            Z0 += fast_exp2(a0[i] - m0);
            Z1 += fast_exp2(a1[i] - m1);
        }
    }
    mh2[h * 128 + cp] = make_float2(m0, m1);
    Zh2[h * 128 + cp] = make_float2(Z0, Z1);
    yh2[h * 128 + cp] = make_float2(y0, y1);
    __syncthreads();

    // ---- combine column stats (h==0) -> bq ----
    if (h == 0) {
        float2 ma = mh2[cp], mb = mh2[128 + cp], mc = mh2[256 + cp], md = mh2[384 + cp];
        float mx0 = fmaxf(fmaxf(ma.x, mb.x), fmaxf(mc.x, md.x));
        float mx1 = fmaxf(fmaxf(ma.y, mb.y), fmaxf(mc.y, md.y));
        float2 za = Zh2[cp], zb = Zh2[128 + cp], zc = Zh2[256 + cp], zd = Zh2[384 + cp];
        float Zt0 = za.x * fast_exp2(ma.x - mx0) + zb.x * fast_exp2(mb.x - mx0)
                  + zc.x * fast_exp2(mc.x - mx0) + zd.x * fast_exp2(md.x - mx0);
        float Zt1 = za.y * fast_exp2(ma.y - mx1) + zb.y * fast_exp2(mb.y - mx1)
                  + zc.y * fast_exp2(mc.y - mx1) + zd.y * fast_exp2(md.y - mx1);
        bq[2 * cp]     = make_float2(ww.x, -mx0 - fast_lg2(Zt0));
        bq[2 * cp + 1] = make_float2(ww.y, -mx1 - fast_lg2(Zt1));
    }
    __syncthreads();

    // ---- pass B: s_j over columns cc in [rbase, rbase+64), j = c0,c1 ----
    {
        float s0 = 0.f, s1 = 0.f;
#pragma unroll 16
        for (int cc = rbase; cc < rbase + RH4; cc++) {
            float2 g = G2v[cc * 128 + cp];         // G2[cc][c0], G2[cc][c1]
            float2 t = bq[cc];                     // broadcast
            s0 += fast_exp2(fmaf(t.x * rr.x, g.x, t.y));
            s1 += fast_exp2(fmaf(t.x * rr.y, g.y, t.y));
        }
        sh2[h * 128 + cp] = make_float2(s0, s1);
    }
    __syncthreads();

    // ---- u (h==0 only) ----
    float st0 = 0.f, st1 = 0.f, u0 = 0.f, u1 = 0.f;
    if (h == 0) {
        float2 sa = sh2[cp], sb = sh2[128 + cp], sc = sh2[256 + cp], sd = sh2[384 + cp];
        st0 = ((sa.x + sb.x) + (sc.x + sd.x)) * fast_exp2(p20);
        st1 = ((sa.y + sb.y) + (sc.y + sd.y)) * fast_exp2(p21);
        u0 = st0 * rr.x;
        u1 = st1 * rr.y;
        us[2 * cp] = u0;
        us[2 * cp + 1] = u1;
    }
    __syncthreads();

    // ---- pass C: z = G*u partials ----
    {
        float z0 = 0.f, z1 = 0.f;
#pragma unroll 16
        for (int r = rbase; r < rbase + RH4; r++) {
            float2 g = G2v[r * 128 + cp];
            float uu = us[r];                      // broadcast
            z0 = fmaf(g.x, uu, z0);
            z1 = fmaf(g.y, uu, z1);
        }
        zh2[h * 128 + cp] = make_float2(z0, z1);
    }
    __syncthreads();

    // ---- reductions (h==0 contributes): T0=r.y T1=u.y T2=u.z T3=r.v T4=u.v T5=S --
    float t0 = 0.f, t1 = 0.f, t2 = 0.f, t3 = 0.f, t4 = 0.f, t5 = 0.f;
    if (h == 0) {
        float2 ya = yh2[cp], yb = yh2[128 + cp], yc = yh2[256 + cp], yd = yh2[384 + cp];
        float y0t = (ya.x + yb.x) + (yc.x + yd.x);
        float y1t = (ya.y + yb.y) + (yc.y + yd.y);
        float2 za = zh2[cp], zb = zh2[128 + cp], zc = zh2[256 + cp], zd = zh2[384 + cp];
        float z0t = (za.x + zb.x) + (zc.x + zd.x);
        float z1t = (za.y + zb.y) + (zc.y + zd.y);
        t0 = rr.x * y0t + rr.y * y1t;
        t1 = u0 * y0t + u1 * y1t;
        t2 = u0 * z0t + u1 * z1t;
        t3 = rr.x * vv.x + rr.y * vv.y;
        t4 = u0 * vv.x + u1 * vv.y;
        t5 = st0 + st1;
    }
#pragma unroll
    for (int o = 16; o; o >>= 1) {
        t0 += __shfl_down_sync(0xffffffffu, t0, o);
        t1 += __shfl_down_sync(0xffffffffu, t1, o);
        t2 += __shfl_down_sync(0xffffffffu, t2, o);
        t3 += __shfl_down_sync(0xffffffffu, t3, o);
        t4 += __shfl_down_sync(0xffffffffu, t4, o);
        t5 += __shfl_down_sync(0xffffffffu, t5, o);
    }
    if ((tid & 31) == 0) {
        int w = tid >> 5;
        red[w * 6 + 0] = t0; red[w * 6 + 1] = t1; red[w * 6 + 2] = t2;
        red[w * 6 + 3] = t3; red[w * 6 + 4] = t4; red[w * 6 + 5] = t5;
    }
    __syncthreads();
    if (tid == 0) {
        float T0 = 0, T1 = 0, T2 = 0, T3 = 0, T4 = 0, S = 0;
#pragma unroll
        for (int w = 0; w < 4; w++) {             // only warps 0-3 contribute (h==0)
            T0 += red[w * 6 + 0]; T1 += red[w * 6 + 1]; T2 += red[w * 6 + 2];
            T3 += red[w * 6 + 3]; T4 += red[w * 6 + 4]; S  += red[w * 6 + 5];
        }
        float c_un = g_c2 * INVL2E;
        const float Tf = (float)NT;
        float num = (T1 + S * T3 + Tf * T4) * INVL2E + Tf * S * c_un;
        float n1s = (T0 + 2.0f * Tf * T3) * INVL2E + Tf * Tf * c_un;
        float n2s = (T2 + 2.0f * S * T4) * INVL2E + S * S * c_un;
        float denom = fmaxf(sqrtf(n1s) * sqrtf(n2s), 1e-8f * Tf * Tf);
        out[b] = 3.0f * num / denom;
    }
}

extern "C" void kernel_launch(void* const* d_in, const int* in_sizes, int n_in,
                              void* d_out, int out_size) {
    const float* req  = (const float*)d_in[0];   // [B,T]
    const float* wsdl = (const float*)d_in[1];   // [B,T]
    const float* te   = (const float*)d_in[2];   // [E,T]
    const float* wf   = (const float*)d_in[3];   // [T,E]
    const float* bf   = (const float*)d_in[4];   // [T]
    float* out = (float*)d_out;                  // [B]

    dim3 grd(16, 16);
    k_M<<<grd, 256>>>(te, wf);
    k_Gv<<<grd, 256>>>(bf);
    k_fused<<<NB, NTH>>>(req, wsdl, out);
}